// round 6
// baseline (speedup 1.0000x reference)
#include <cuda_runtime.h>
#include <math.h>

typedef unsigned long long u64;

#define NPTS 65536
#define KC   4096
#define DD   64
#define BM   128
#define BN   128
#define PAD  4
#define SROW (BM + PAD)      /* 132 floats: padded row stride for transposed tiles */
#define NTHREADS 256

/* ------- device scratch (no allocations allowed) ------- */
__device__ float g_e2[KC];
__device__ int   g_counts[KC];
__device__ float g_sqsum;
__device__ int   g_idx[NPTS];

/* ------- packed f32x2 helpers (sm_100+ PTX) ------- */
__device__ __forceinline__ u64 pack2(float lo, float hi) {
    u64 r; asm("mov.b64 %0, {%1, %2};" : "=l"(r) : "f"(lo), "f"(hi)); return r;
}
__device__ __forceinline__ void unpack2(u64 v, float &lo, float &hi) {
    asm("mov.b64 {%0, %1}, %2;" : "=f"(lo), "=f"(hi) : "l"(v));
}
__device__ __forceinline__ u64 ffma2(u64 a, u64 b, u64 c) {
    u64 d; asm("fma.rn.f32x2 %0, %1, %2, %3;" : "=l"(d) : "l"(a), "l"(b), "l"(c)); return d;
}

/* ------- K0: zero scratch (graph replays must be deterministic) ------- */
__global__ void k_zero() {
    int t = blockIdx.x * blockDim.x + threadIdx.x;
    if (t < KC) g_counts[t] = 0;
    if (t == 0) g_sqsum = 0.0f;
}

/* ------- K1: e2[k] = sum_d e[k][d]^2, sequential fp32 (no fma contraction) ------- */
__global__ void k_e2(const float* __restrict__ emb) {
    int k = blockIdx.x * blockDim.x + threadIdx.x;
    if (k >= KC) return;
    const float* row = emb + (size_t)k * DD;
    float s = 0.0f;
#pragma unroll
    for (int d = 0; d < DD; d++) s = __fadd_rn(s, __fmul_rn(row[d], row[d]));
    g_e2[k] = s;
}

/* ------- K2: fused distance GEMM + streaming argmin -------
 * dist[n][k] = fl( fl(z2[n] + e2[k]) - fl(2 * dot(z[n], e[k])) ), argmin tie -> lowest k.
 * Block tile: 128 rows x 128 codes, loop over K in chunks of 128.
 * Per-thread micro-tile 8x8, accumulators as f32x2 pairs (row pairs). */
extern __shared__ float smem_dyn[];

__global__ __launch_bounds__(NTHREADS)
void k_argmin(const float* __restrict__ z, const float* __restrict__ emb) {
    float* zs  = smem_dyn;               /* [DD][SROW] transposed z tile   */
    float* es  = zs + DD * SROW;         /* [DD][SROW] transposed emb tile */
    float* z2s = es + DD * SROW;         /* [BM] */
    float* e2s = z2s + BM;               /* [BN] */

    const int tid = threadIdx.x;
    const int n0  = blockIdx.x * BM;

    /* load z tile (coalesced global float4) and transpose into smem */
#pragma unroll
    for (int i = 0; i < 8; i++) {
        int lin = tid + i * NTHREADS;    /* 0..2047: 128 rows x 16 float4 */
        int r   = lin >> 4;
        int d4  = lin & 15;
        float4 v = *reinterpret_cast<const float4*>(z + (size_t)(n0 + r) * DD + d4 * 4);
        zs[(d4 * 4 + 0) * SROW + r] = v.x;
        zs[(d4 * 4 + 1) * SROW + r] = v.y;
        zs[(d4 * 4 + 2) * SROW + r] = v.z;
        zs[(d4 * 4 + 3) * SROW + r] = v.w;
    }
    /* z2 per row, sequential fp32 order matching k_e2 */
    if (tid < BM) {
        const float* row = z + (size_t)(n0 + tid) * DD;
        float s = 0.0f;
#pragma unroll
        for (int d = 0; d < DD; d++) s = __fadd_rn(s, __fmul_rn(row[d], row[d]));
        z2s[tid] = s;
    }
    __syncthreads();

    const int ty = tid >> 4;             /* 16 row-groups  */
    const int tx = tid & 15;             /* 16 code-groups */
    const int r0 = ty * 8;
    const int c0 = tx * 8;

    float z2r[8];
#pragma unroll
    for (int i = 0; i < 8; i++) z2r[i] = z2s[r0 + i];

    float best[8]; int bidx[8];
#pragma unroll
    for (int i = 0; i < 8; i++) { best[i] = 3.4e38f; bidx[i] = 0; }

    for (int k0 = 0; k0 < KC; k0 += BN) {
        /* load emb tile transposed */
#pragma unroll
        for (int i = 0; i < 8; i++) {
            int lin = tid + i * NTHREADS;
            int c   = lin >> 4;
            int d4  = lin & 15;
            float4 v = *reinterpret_cast<const float4*>(emb + (size_t)(k0 + c) * DD + d4 * 4);
            es[(d4 * 4 + 0) * SROW + c] = v.x;
            es[(d4 * 4 + 1) * SROW + c] = v.y;
            es[(d4 * 4 + 2) * SROW + c] = v.z;
            es[(d4 * 4 + 3) * SROW + c] = v.w;
        }
        if (tid < BN) e2s[tid] = g_e2[k0 + tid];
        __syncthreads();

        u64 acc[4][8];                    /* [row-pair][code] */
#pragma unroll
        for (int p = 0; p < 4; p++)
#pragma unroll
            for (int c = 0; c < 8; c++) acc[p][c] = 0ULL;

        const float* zp_base = zs + r0;
        const float* ep_base = es + c0;
#pragma unroll 8
        for (int d = 0; d < DD; d++) {
            const float* zrow = zp_base + d * SROW;
            const float* erow = ep_base + d * SROW;
            float4 za = *reinterpret_cast<const float4*>(zrow);
            float4 zb = *reinterpret_cast<const float4*>(zrow + 4);
            float4 ea = *reinterpret_cast<const float4*>(erow);
            float4 eb = *reinterpret_cast<const float4*>(erow + 4);
            u64 zp[4];
            zp[0] = pack2(za.x, za.y);
            zp[1] = pack2(za.z, za.w);
            zp[2] = pack2(zb.x, zb.y);
            zp[3] = pack2(zb.z, zb.w);
            float ef[8] = {ea.x, ea.y, ea.z, ea.w, eb.x, eb.y, eb.z, eb.w};
#pragma unroll
            for (int c = 0; c < 8; c++) {
                u64 ed = pack2(ef[c], ef[c]);
#pragma unroll
                for (int p = 0; p < 4; p++) acc[p][c] = ffma2(zp[p], ed, acc[p][c]);
            }
        }

        /* chunk epilogue: dist + running argmin (ascending code order, strict <) */
#pragma unroll
        for (int c = 0; c < 8; c++) {
            float e2v = e2s[c0 + c];
            int   gid = k0 + c0 + c;
#pragma unroll
            for (int p = 0; p < 4; p++) {
                float d0, d1; unpack2(acc[p][c], d0, d1);
                float A0 = __fadd_rn(z2r[2 * p],     e2v);
                float A1 = __fadd_rn(z2r[2 * p + 1], e2v);
                float x0 = __fsub_rn(A0, __fmul_rn(2.0f, d0));
                float x1 = __fsub_rn(A1, __fmul_rn(2.0f, d1));
                if (x0 < best[2 * p])     { best[2 * p]     = x0; bidx[2 * p]     = gid; }
                if (x1 < best[2 * p + 1]) { best[2 * p + 1] = x1; bidx[2 * p + 1] = gid; }
            }
        }
        __syncthreads();
    }

    /* reduce over the 16 code-group lanes (same ty = 16 consecutive lanes) */
#pragma unroll
    for (int off = 1; off < 16; off <<= 1) {
#pragma unroll
        for (int i = 0; i < 8; i++) {
            float ob = __shfl_xor_sync(0xffffffffu, best[i], off);
            int   oi = __shfl_xor_sync(0xffffffffu, bidx[i], off);
            if (ob < best[i] || (ob == best[i] && oi < bidx[i])) { best[i] = ob; bidx[i] = oi; }
        }
    }
    if (tx == 0) {
#pragma unroll
        for (int i = 0; i < 8; i++) g_idx[n0 + r0 + i] = bidx[i];
    }
}

/* ------- K3: gather z_q, write z_q_st + indices, accumulate sq-loss + counts ------- */
__global__ __launch_bounds__(256)
void k_gather(const float* __restrict__ z, const float* __restrict__ emb,
              float* __restrict__ out) {
    __shared__ float red[256];
    const int tid  = threadIdx.x;
    const int base = blockIdx.x * 512;                 /* 128 blocks x 512 rows */
    float acc = 0.0f;
    const size_t ND = (size_t)NPTS * DD;

    for (int i = 0; i < 32; i++) {
        int lin = tid + i * 256;                        /* 512 rows x 16 float4 */
        int r   = lin >> 4;
        int d4  = lin & 15;
        int n   = base + r;
        int idx = g_idx[n];
        float4 e4 = *reinterpret_cast<const float4*>(emb + (size_t)idx * DD + d4 * 4);
        float4 z4 = *reinterpret_cast<const float4*>(z + (size_t)n * DD + d4 * 4);
        *reinterpret_cast<float4*>(out + (size_t)n * DD + d4 * 4) = e4;
        float dx = e4.x - z4.x, dy = e4.y - z4.y, dz = e4.z - z4.z, dw = e4.w - z4.w;
        acc += dx * dx + dy * dy + dz * dz + dw * dw;
        if (d4 == 0) {
            atomicAdd(&g_counts[idx], 1);
            out[ND + 3 + n] = (float)idx;
        }
    }
    red[tid] = acc;
    __syncthreads();
    for (int s = 128; s > 0; s >>= 1) {
        if (tid < s) red[tid] += red[tid + s];
        __syncthreads();
    }
    if (tid == 0) atomicAdd(&g_sqsum, red[0]);
}

/* ------- K4: losses, perplexity, active codes ------- */
__global__ void k_final(float* __restrict__ out) {
    __shared__ float sH[256];
    __shared__ int   sA[256];
    int tid = threadIdx.x;
    float H = 0.0f; int active = 0;
    for (int i = tid; i < KC; i += 256) {
        float p = (float)g_counts[i] * (1.0f / 65536.0f);
        H += p * logf(p + 1e-10f);
        if (p > 0.0f) active++;
    }
    sH[tid] = H; sA[tid] = active;
    __syncthreads();
    for (int s = 128; s > 0; s >>= 1) {
        if (tid < s) { sH[tid] += sH[tid + s]; sA[tid] += sA[tid + s]; }
        __syncthreads();
    }
    if (tid == 0) {
        const size_t ND = (size_t)NPTS * DD;
        float mse = g_sqsum / (float)(NPTS * DD);       /* codebook == commit numerically */
        out[ND]     = __fadd_rn(mse, __fmul_rn(0.25f, mse));  /* vq_loss */
        out[ND + 1] = mse;                                    /* codebook_loss */
        out[ND + 2] = mse;                                    /* commit_loss */
        out[ND + 3 + NPTS] = expf(-sH[0]);                    /* perplexity */
        out[ND + 4 + NPTS] = (float)sA[0];                    /* active_codes */
    }
}

extern "C" void kernel_launch(void* const* d_in, const int* in_sizes, int n_in,
                              void* d_out, int out_size) {
    const float *z, *emb;
    if (in_sizes[0] == KC * DD) { emb = (const float*)d_in[0]; z = (const float*)d_in[1]; }
    else                        { z   = (const float*)d_in[0]; emb = (const float*)d_in[1]; }
    float* out = (float*)d_out;

    size_t smem = (size_t)(DD * SROW * 2 + BM + BN) * sizeof(float);   /* 68608 B */
    cudaFuncSetAttribute(k_argmin, cudaFuncAttributeMaxDynamicSharedMemorySize, (int)smem);

    k_zero <<<(KC + 255) / 256, 256>>>();
    k_e2   <<<(KC + 255) / 256, 256>>>(emb);
    k_argmin<<<NPTS / BM, NTHREADS, smem>>>(z, emb);
    k_gather<<<128, 256>>>(z, emb, out);
    k_final<<<1, 256>>>(out);
}

// round 10
// speedup vs baseline: 2.9068x; 2.9068x over previous
#include <cuda_runtime.h>
#include <cuda_fp16.h>
#include <math.h>
#include <stdint.h>

typedef unsigned long long u64;

#define NPTS 65536
#define KC   4096
#define DD   64
#define BM   128
#define BN   128
#define PAD  4
#define SROW (BM + PAD)
#define NTHREADS 256
#define THETA 3e-5f

/* k_hmma smem offsets (from 128B-aligned base) */
#define SA   0          /* A tile: 128 rows x 128B (swizzled) */
#define SB0  16384
#define SB1  32768
#define SE0  49152      /* e2 chunk: 128 floats */
#define SE1  49664
#define SMEM_H (50176 + 128)

/* ---------------- device scratch ---------------- */
__device__ float g_e2[KC];
__device__ int   g_counts[KC];
__device__ float g_sqsum;
__device__ int   g_idx[NPTS];
__device__ int   g_flag_cnt;
__device__ int   g_flag_list[NPTS];
__device__ u64   g_pack[NPTS];
__device__ __align__(16) __half g_Ah[(size_t)NPTS * DD];  /* 8 MB */
__device__ __align__(16) __half g_Bh[(size_t)KC * DD];    /* 512 KB */

extern __shared__ char smdyn[];

/* ---------------- helpers ---------------- */
__device__ __forceinline__ uint32_t smem_u32(const void* p) {
    uint32_t a;
    asm("{ .reg .u64 t; cvta.to.shared.u64 t, %1; cvt.u32.u64 %0, t; }" : "=r"(a) : "l"(p));
    return a;
}
__device__ __forceinline__ u64 pack2(float lo, float hi) {
    u64 r; asm("mov.b64 %0, {%1, %2};" : "=l"(r) : "f"(lo), "f"(hi)); return r;
}
__device__ __forceinline__ void unpack2(u64 v, float &lo, float &hi) {
    asm("mov.b64 {%0, %1}, %2;" : "=f"(lo), "=f"(hi) : "l"(v));
}
__device__ __forceinline__ u64 ffma2(u64 a, u64 b, u64 c) {
    u64 d; asm("fma.rn.f32x2 %0, %1, %2, %3;" : "=l"(d) : "l"(a), "l"(b), "l"(c)); return d;
}
__device__ __forceinline__ void ldm4(uint32_t* r, uint32_t addr) {
    asm volatile("ldmatrix.sync.aligned.m8n8.x4.shared.b16 {%0,%1,%2,%3}, [%4];"
        : "=r"(r[0]), "=r"(r[1]), "=r"(r[2]), "=r"(r[3]) : "r"(addr));
}
__device__ __forceinline__ void mma16816(float* c, const uint32_t* a, const uint32_t* b) {
    asm volatile("mma.sync.aligned.m16n8k16.row.col.f32.f16.f16.f32 "
        "{%0,%1,%2,%3}, {%4,%5,%6,%7}, {%8,%9}, {%0,%1,%2,%3};"
        : "+f"(c[0]), "+f"(c[1]), "+f"(c[2]), "+f"(c[3])
        : "r"(a[0]), "r"(a[1]), "r"(a[2]), "r"(a[3]), "r"(b[0]), "r"(b[1]));
}
__device__ __forceinline__ void cpa16(uint32_t dst, const void* src) {
    asm volatile("cp.async.cg.shared.global [%0], [%1], 16;" :: "r"(dst), "l"(src) : "memory");
}

/* ------- K0: zero scratch ------- */
__global__ void k_zero() {
    int t = blockIdx.x * blockDim.x + threadIdx.x;
    if (t < KC) g_counts[t] = 0;
    if (t == 0) { g_sqsum = 0.0f; g_flag_cnt = 0; }
}

/* ------- prep: e2 (exact sequential fp32) + fp16 copies ------- */
__global__ __launch_bounds__(256) void k_prep_e(const float* __restrict__ emb) {
    int k = blockIdx.x * blockDim.x + threadIdx.x;
    if (k >= KC) return;
    const float* row = emb + (size_t)k * DD;
    float s = 0.0f;
#pragma unroll
    for (int d = 0; d < DD; d++) s = __fadd_rn(s, __fmul_rn(row[d], row[d]));
    g_e2[k] = s;
    __half2* dst = (__half2*)(g_Bh + (size_t)k * DD);
#pragma unroll
    for (int d = 0; d < DD / 2; d++) dst[d] = __floats2half2_rn(row[2 * d], row[2 * d + 1]);
}
__global__ __launch_bounds__(256) void k_prep_z(const float* __restrict__ z) {
    int i = blockIdx.x * blockDim.x + threadIdx.x;     /* over N*D/2 */
    float2 v = ((const float2*)z)[i];
    ((__half2*)g_Ah)[i] = __floats2half2_rn(v.x, v.y);
}

/* ------- K2: fp16 HMMA distance-proxy GEMM + running argmin + margin flag -------
 * proxy y[n][k] = e2[k] - 2*(zh[n].eh[k]); per-row argmin invariant to +z2.
 * CTA: 128 rows x (K loop: 32 chunks of 128 codes). 8 warps: wm=wid&3 (32 rows),
 * wn=wid>>2 (64 cols). A fragments cached in registers across all chunks. */
__global__ __launch_bounds__(256)
void k_hmma() {
    char* sm = (char*)((((uintptr_t)smdyn) + 127) & ~(uintptr_t)127);
    const uint32_t smb = smem_u32(sm);
    const int tid = threadIdx.x;
    const int l   = tid & 31;
    const int wid = tid >> 5;
    const int m0  = (wid & 3) * 32;
    const int nb  = (wid >> 2) * 64;

    /* prologue: A tile + B chunk0 + e2 chunk0 via cp.async (pre-swizzled dst) */
    {
        const char* gA = (const char*)(g_Ah + (size_t)blockIdx.x * BM * DD);
#pragma unroll
        for (int i = 0; i < 4; i++) {
            int lin = tid + i * 256;                    /* 1024 x 16B */
            int row = lin >> 3, u = lin & 7;
            cpa16(smb + SA + row * 128 + ((u ^ (row & 7)) << 4), gA + lin * 16);
        }
#pragma unroll
        for (int i = 0; i < 4; i++) {
            int lin = tid + i * 256;
            int row = lin >> 3, u = lin & 7;
            cpa16(smb + SB0 + row * 128 + ((u ^ (row & 7)) << 4), (const char*)g_Bh + lin * 16);
        }
        if (tid < 32) cpa16(smb + SE0 + tid * 16, (const char*)g_e2 + tid * 16);
        asm volatile("cp.async.commit_group;" ::: "memory");
        asm volatile("cp.async.wait_group 0;" ::: "memory");
        __syncthreads();
    }

    /* cache A fragments: 2 m-tiles x 4 k-steps x 4 regs */
    uint32_t a[2][4][4];
#pragma unroll
    for (int mt = 0; mt < 2; mt++)
#pragma unroll
        for (int ks = 0; ks < 4; ks++) {
            int row = m0 + mt * 16 + (l & 7) + ((l >> 3) & 1) * 8;
            int u   = ks * 2 + (l >> 4);
            ldm4(a[mt][ks], smb + SA + row * 128 + ((u ^ (row & 7)) << 4));
        }

    float b1[4], b2[4]; int i1[4];
#pragma unroll
    for (int s = 0; s < 4; s++) { b1[s] = 3.4e38f; b2[s] = 3.4e38f; i1[s] = 0; }

    for (int c = 0; c < 32; c++) {
        const int cur = c & 1;
        __syncthreads();                                /* buf 1-cur free (chunk c-1 done) */
        if (c + 1 < 32) {
            const char* gB = (const char*)g_Bh + (size_t)(c + 1) * 16384;
            uint32_t bb = smb + (cur ? SB0 : SB1);
#pragma unroll
            for (int i = 0; i < 4; i++) {
                int lin = tid + i * 256;
                int row = lin >> 3, u = lin & 7;
                cpa16(bb + row * 128 + ((u ^ (row & 7)) << 4), gB + lin * 16);
            }
            if (tid < 32) cpa16(smb + (cur ? SE0 : SE1) + tid * 16,
                                (const char*)g_e2 + (c + 1) * 512 + tid * 16);
            asm volatile("cp.async.commit_group;" ::: "memory");
            asm volatile("cp.async.wait_group 1;" ::: "memory");
        } else {
            asm volatile("cp.async.wait_group 0;" ::: "memory");
        }
        __syncthreads();                                /* buf cur complete & visible */

        const uint32_t bbase = smb + (cur ? SB1 : SB0);
        const char*    ebase = sm + (cur ? SE1 : SE0);
        float e2v[8][2];
#pragma unroll
        for (int nt = 0; nt < 8; nt++)
#pragma unroll
            for (int j = 0; j < 2; j++)
                e2v[nt][j] = *(const float*)(ebase + (nb + nt * 8 + (l & 3) * 2 + j) * 4);

        float cc[2][8][4];
#pragma unroll
        for (int mt = 0; mt < 2; mt++)
#pragma unroll
            for (int nt = 0; nt < 8; nt++)
#pragma unroll
                for (int q = 0; q < 4; q++) cc[mt][nt][q] = 0.0f;

#pragma unroll
        for (int ks = 0; ks < 4; ks++) {
            uint32_t b[8][2];
#pragma unroll
            for (int g = 0; g < 4; g++) {
                int row = nb + g * 16 + (l & 7) + ((l >> 4) & 1) * 8;
                int u   = ks * 2 + ((l >> 3) & 1);
                uint32_t r4[4];
                ldm4(r4, bbase + row * 128 + ((u ^ (row & 7)) << 4));
                b[g * 2][0] = r4[0]; b[g * 2][1] = r4[1];
                b[g * 2 + 1][0] = r4[2]; b[g * 2 + 1][1] = r4[3];
            }
#pragma unroll
            for (int mt = 0; mt < 2; mt++)
#pragma unroll
                for (int nt = 0; nt < 8; nt++)
                    mma16816(cc[mt][nt], a[mt][ks], b[nt]);
        }

        const int gb0 = c * BN + nb + (l & 3) * 2;
#pragma unroll
        for (int mt = 0; mt < 2; mt++)
#pragma unroll
            for (int nt = 0; nt < 8; nt++)
#pragma unroll
                for (int rh = 0; rh < 2; rh++)
#pragma unroll
                    for (int j = 0; j < 2; j++) {
                        float y = __fmaf_rn(-2.0f, cc[mt][nt][rh * 2 + j], e2v[nt][j]);
                        int s = mt * 2 + rh;
                        int gid = gb0 + nt * 8 + j;
                        bool lt = y < b1[s];
                        b2[s] = fminf(b2[s], lt ? b1[s] : y);
                        if (lt) { b1[s] = y; i1[s] = gid; }
                    }
    }

    /* reduce 4 lanes sharing each row (xor over low 2 bits of lane) */
#pragma unroll
    for (int off = 1; off < 4; off <<= 1) {
#pragma unroll
        for (int s = 0; s < 4; s++) {
            float ob1 = __shfl_xor_sync(0xffffffffu, b1[s], off);
            float ob2 = __shfl_xor_sync(0xffffffffu, b2[s], off);
            int   oi  = __shfl_xor_sync(0xffffffffu, i1[s], off);
            float hi = fmaxf(b1[s], ob1);
            b2[s] = fminf(fminf(b2[s], ob2), hi);
            if (ob1 < b1[s] || (ob1 == b1[s] && oi < i1[s])) { b1[s] = ob1; i1[s] = oi; }
        }
    }

    /* merge col-halves (wn=0 vs wn=1) via smem (reuse A region) */
    __syncthreads();
    float* m1 = (float*)sm;
    float* m2 = m1 + 128;
    int*   mi = (int*)(m2 + 128);
    if (wid >= 4 && (l & 3) == 0) {
#pragma unroll
        for (int s = 0; s < 4; s++) {
            int r = m0 + (s >> 1) * 16 + (s & 1) * 8 + (l >> 2);
            m1[r] = b1[s]; m2[r] = b2[s]; mi[r] = i1[s];
        }
    }
    __syncthreads();
    if (wid < 4 && (l & 3) == 0) {
#pragma unroll
        for (int s = 0; s < 4; s++) {
            int r = m0 + (s >> 1) * 16 + (s & 1) * 8 + (l >> 2);
            float ob1 = m1[r], ob2 = m2[r]; int oi = mi[r];
            float hi = fmaxf(b1[s], ob1);
            float nb2 = fminf(fminf(b2[s], ob2), hi);
            float nb1 = b1[s]; int ni = i1[s];
            if (ob1 < nb1 || (ob1 == nb1 && oi < ni)) { nb1 = ob1; ni = oi; }
            int row = blockIdx.x * BM + r;
            g_idx[row] = ni;
            if (nb2 - nb1 < THETA) {
                int p = atomicAdd(&g_flag_cnt, 1);
                g_flag_list[p] = row;
                g_pack[p] = ~0ULL;
            }
        }
    }
}

/* ------- K3: exact fp32 rescue (round-3 formula verbatim), K split 4 ways ------- */
__global__ __launch_bounds__(NTHREADS)
void k_rescue(const float* __restrict__ z, const float* __restrict__ emb) {
    float* smf = (float*)smdyn;
    __shared__ int rl[BM];
    float* zs  = smf;
    float* es  = zs + DD * SROW;
    float* z2s = es + DD * SROW;
    float* e2s = z2s + BM;
    const int tid = threadIdx.x;
    const int cnt = g_flag_cnt;
    const int kseg = blockIdx.y * (KC / 4);

    for (int tile = blockIdx.x; tile * BM < cnt; tile += gridDim.x) {
        const int n0 = tile * BM;
        const int nrows = min(BM, cnt - n0);
        if (tid < BM) rl[tid] = g_flag_list[n0 + min(tid, nrows - 1)];
        __syncthreads();

#pragma unroll
        for (int i = 0; i < 8; i++) {
            int lin = tid + i * NTHREADS;
            int r = lin >> 4, d4 = lin & 15;
            float4 v = *reinterpret_cast<const float4*>(z + (size_t)rl[r] * DD + d4 * 4);
            zs[(d4 * 4 + 0) * SROW + r] = v.x;
            zs[(d4 * 4 + 1) * SROW + r] = v.y;
            zs[(d4 * 4 + 2) * SROW + r] = v.z;
            zs[(d4 * 4 + 3) * SROW + r] = v.w;
        }
        if (tid < BM) {
            const float* row = z + (size_t)rl[tid] * DD;
            float s = 0.0f;
#pragma unroll
            for (int d = 0; d < DD; d++) s = __fadd_rn(s, __fmul_rn(row[d], row[d]));
            z2s[tid] = s;
        }
        __syncthreads();

        const int ty = tid >> 4, tx = tid & 15;
        const int r0 = ty * 8, c0 = tx * 8;
        float z2r[8];
#pragma unroll
        for (int i = 0; i < 8; i++) z2r[i] = z2s[r0 + i];
        float best[8]; int bidx[8];
#pragma unroll
        for (int i = 0; i < 8; i++) { best[i] = 3.4e38f; bidx[i] = 0; }

        for (int kk = 0; kk < KC / 4; kk += BN) {
            const int k0 = kseg + kk;
#pragma unroll
            for (int i = 0; i < 8; i++) {
                int lin = tid + i * NTHREADS;
                int cc = lin >> 4, d4 = lin & 15;
                float4 v = *reinterpret_cast<const float4*>(emb + (size_t)(k0 + cc) * DD + d4 * 4);
                es[(d4 * 4 + 0) * SROW + cc] = v.x;
                es[(d4 * 4 + 1) * SROW + cc] = v.y;
                es[(d4 * 4 + 2) * SROW + cc] = v.z;
                es[(d4 * 4 + 3) * SROW + cc] = v.w;
            }
            if (tid < BN) e2s[tid] = g_e2[k0 + tid];
            __syncthreads();

            u64 acc[4][8];
#pragma unroll
            for (int p = 0; p < 4; p++)
#pragma unroll
                for (int cc = 0; cc < 8; cc++) acc[p][cc] = 0ULL;

            const float* zp_base = zs + r0;
            const float* ep_base = es + c0;
#pragma unroll 8
            for (int d = 0; d < DD; d++) {
                const float* zrow = zp_base + d * SROW;
                const float* erow = ep_base + d * SROW;
                float4 za = *reinterpret_cast<const float4*>(zrow);
                float4 zb = *reinterpret_cast<const float4*>(zrow + 4);
                float4 ea = *reinterpret_cast<const float4*>(erow);
                float4 eb = *reinterpret_cast<const float4*>(erow + 4);
                u64 zp[4];
                zp[0] = pack2(za.x, za.y); zp[1] = pack2(za.z, za.w);
                zp[2] = pack2(zb.x, zb.y); zp[3] = pack2(zb.z, zb.w);
                float ef[8] = {ea.x, ea.y, ea.z, ea.w, eb.x, eb.y, eb.z, eb.w};
#pragma unroll
                for (int cc = 0; cc < 8; cc++) {
                    u64 ed = pack2(ef[cc], ef[cc]);
#pragma unroll
                    for (int p = 0; p < 4; p++) acc[p][cc] = ffma2(zp[p], ed, acc[p][cc]);
                }
            }
#pragma unroll
            for (int cc = 0; cc < 8; cc++) {
                float e2v = e2s[c0 + cc];
                int gid = k0 + c0 + cc;
#pragma unroll
                for (int p = 0; p < 4; p++) {
                    float d0, d1; unpack2(acc[p][cc], d0, d1);
                    float A0 = __fadd_rn(z2r[2 * p],     e2v);
                    float A1 = __fadd_rn(z2r[2 * p + 1], e2v);
                    float x0 = __fsub_rn(A0, __fmul_rn(2.0f, d0));
                    float x1 = __fsub_rn(A1, __fmul_rn(2.0f, d1));
                    if (x0 < best[2 * p])     { best[2 * p]     = x0; bidx[2 * p]     = gid; }
                    if (x1 < best[2 * p + 1]) { best[2 * p + 1] = x1; bidx[2 * p + 1] = gid; }
                }
            }
            __syncthreads();
        }
#pragma unroll
        for (int off = 1; off < 16; off <<= 1) {
#pragma unroll
            for (int i = 0; i < 8; i++) {
                float ob = __shfl_xor_sync(0xffffffffu, best[i], off);
                int   oi = __shfl_xor_sync(0xffffffffu, bidx[i], off);
                if (ob < best[i] || (ob == best[i] && oi < bidx[i])) { best[i] = ob; bidx[i] = oi; }
            }
        }
        if (tx == 0) {
#pragma unroll
            for (int i = 0; i < 8; i++) {
                int rr = r0 + i;
                if (rr < nrows) {
                    u64 key = ((u64)__float_as_uint(best[i]) << 32) | (u64)(unsigned)bidx[i];
                    atomicMin(&g_pack[n0 + rr], key);
                }
            }
        }
        __syncthreads();
    }
}

/* ------- K3b: commit rescued indices ------- */
__global__ void k_fixup() {
    int cnt = g_flag_cnt;
    for (int p = blockIdx.x * blockDim.x + threadIdx.x; p < cnt; p += gridDim.x * blockDim.x)
        g_idx[g_flag_list[p]] = (int)(g_pack[p] & 0xFFFFFFFFULL);
}

/* ------- K4: gather z_q, losses, counts ------- */
__global__ __launch_bounds__(256)
void k_gather(const float* __restrict__ z, const float* __restrict__ emb,
              float* __restrict__ out) {
    __shared__ float red[256];
    const int tid  = threadIdx.x;
    const int base = blockIdx.x * 512;
    float acc = 0.0f;
    const size_t ND = (size_t)NPTS * DD;

    for (int i = 0; i < 32; i++) {
        int lin = tid + i * 256;
        int r = lin >> 4, d4 = lin & 15;
        int n = base + r;
        int idx = g_idx[n];
        float4 e4 = *reinterpret_cast<const float4*>(emb + (size_t)idx * DD + d4 * 4);
        float4 z4 = *reinterpret_cast<const float4*>(z + (size_t)n * DD + d4 * 4);
        *reinterpret_cast<float4*>(out + (size_t)n * DD + d4 * 4) = e4;
        float dx = e4.x - z4.x, dy = e4.y - z4.y, dz = e4.z - z4.z, dw = e4.w - z4.w;
        acc += dx * dx + dy * dy + dz * dz + dw * dw;
        if (d4 == 0) {
            atomicAdd(&g_counts[idx], 1);
            out[ND + 3 + n] = (float)idx;
        }
    }
    red[tid] = acc;
    __syncthreads();
    for (int s = 128; s > 0; s >>= 1) {
        if (tid < s) red[tid] += red[tid + s];
        __syncthreads();
    }
    if (tid == 0) atomicAdd(&g_sqsum, red[0]);
}

__global__ void k_final(float* __restrict__ out) {
    __shared__ float sH[256];
    __shared__ int   sA[256];
    int tid = threadIdx.x;
    float H = 0.0f; int active = 0;
    for (int i = tid; i < KC; i += 256) {
        float p = (float)g_counts[i] * (1.0f / 65536.0f);
        H += p * logf(p + 1e-10f);
        if (p > 0.0f) active++;
    }
    sH[tid] = H; sA[tid] = active;
    __syncthreads();
    for (int s = 128; s > 0; s >>= 1) {
        if (tid < s) { sH[tid] += sH[tid + s]; sA[tid] += sA[tid + s]; }
        __syncthreads();
    }
    if (tid == 0) {
        const size_t ND = (size_t)NPTS * DD;
        float mse = g_sqsum / (float)(NPTS * DD);
        out[ND]     = __fadd_rn(mse, __fmul_rn(0.25f, mse));
        out[ND + 1] = mse;
        out[ND + 2] = mse;
        out[ND + 3 + NPTS] = expf(-sH[0]);
        out[ND + 4 + NPTS] = (float)sA[0];
    }
}

extern "C" void kernel_launch(void* const* d_in, const int* in_sizes, int n_in,
                              void* d_out, int out_size) {
    const float *z, *emb;
    if (in_sizes[0] == KC * DD) { emb = (const float*)d_in[0]; z = (const float*)d_in[1]; }
    else                        { z   = (const float*)d_in[0]; emb = (const float*)d_in[1]; }
    float* out = (float*)d_out;

    size_t smemR = (size_t)(DD * SROW * 2 + BM + BN) * sizeof(float);   /* 68608 */
    cudaFuncSetAttribute(k_hmma,   cudaFuncAttributeMaxDynamicSharedMemorySize, SMEM_H);
    cudaFuncSetAttribute(k_rescue, cudaFuncAttributeMaxDynamicSharedMemorySize, (int)smemR);

    k_zero  <<<16, 256>>>();
    k_prep_e<<<16, 256>>>(emb);
    k_prep_z<<<(NPTS * DD / 2) / 256, 256>>>(z);
    k_hmma  <<<NPTS / BM, 256, SMEM_H>>>();
    k_rescue<<<dim3(64, 4), NTHREADS, smemR>>>(z, emb);
    k_fixup <<<16, 256>>>();
    k_gather<<<128, 256>>>(z, emb, out);
    k_final <<<1, 256>>>(out);
}